// round 10
// baseline (speedup 1.0000x reference)
#include <cuda_runtime.h>
#include <cuda_bf16.h>

// PatchEmbed: x (16,64,256,256) f32 -> out (16, 16384, 256) f32  + 4-float shape tail
//
// out[n][j*128 + i][c*4 + ph*2 + pw] = x[n][c][2*i + ph][2*j + pw]
//
// pw pair = float2. Per (n,i) plane: 128x128 float2 transpose between
// J (input-contiguous) and r = c*2+ph (output-contiguous).
//
// R8 profile: DRAM 79.6%, 6.3 TB/s with 256B read chunks. This version widens
// the tile to the FULL j-row: TILE_R=32 x TILE_J=128 float2 (33 KB smem).
// -> reads are contiguous 1KB streams per input row, 8 front-batched LDG.128
//    per thread (MLP 8), 4x fewer CTAs (8192). Writes unchanged (256B/warp-row).
//
// float2-unit strides:
//   input : n: 2097152, c: 32768, i: 256, ph: 128, j: 1
//   output: n: 2097152, j: 16384, i: 128, r: 1

#define TR 32    // r rows per tile
#define TJ 128   // j columns per tile (full row)
#define PAD 2    // float2 pad -> row stride 130 (1040 B, 16B-aligned)

__global__ void patch_transpose_kernel(const float4* __restrict__ x,
                                       float4* __restrict__ out,
                                       float* __restrict__ tail,   // null if absent
                                       long tail_base) {
    __shared__ float2 tile[TR][TJ + PAD];

    const int tr    = blockIdx.x;      // 0..3 : r tile
    const int plane = blockIdx.y;      // n*128 + i
    const int n     = plane >> 7;
    const int i     = plane & 127;
    const int tid   = threadIdx.x;     // 0..255

    if (tail && tr == 0 && plane == 0 && tid == 0) {
        tail[tail_base + 0] = 16.0f;
        tail[tail_base + 1] = 64.0f;
        tail[tail_base + 2] = 256.0f;
        tail[tail_base + 3] = 256.0f;
    }

    // ---- Load: 32 r-rows, each a full 1KB contiguous j-stream (64 float4) ----
    {
        const int  rloc = tid >> 3;            // 0..31
        const int  r    = tr * TR + rloc;      // r = c*2 + ph
        const int  c    = r >> 1;
        const int  ph   = r & 1;
        const long in_f4 = ((long)n * 2097152 + (long)i * 256
                            + (long)c * 32768 + ph * 128) >> 1;
        float4* dst = (float4*)&tile[rloc][0];
        #pragma unroll
        for (int k = 0; k < 8; k++) {
            const int colf4 = (tid & 7) + k * 8;      // 0..63
            dst[colf4] = x[in_f4 + colf4];
        }
    }
    __syncthreads();

    // ---- Store: 128 j-rows, 256B contiguous r-chunk each ----
    {
        const int  r2   = tid & 15;            // float4 index along r (0..15)
        const int  jofs = tid >> 4;            // 0..15
        const long out_base_f4 = ((long)n * 2097152 + (long)i * 128) >> 1;
        #pragma unroll
        for (int k = 0; k < 8; k++) {
            const int j = k * 16 + jofs;       // 0..127
            float2 a = tile[r2 * 2 + 0][j];
            float2 b = tile[r2 * 2 + 1][j];
            out[out_base_f4 + (long)j * 8192 + tr * 16 + r2] =
                make_float4(a.x, a.y, b.x, b.y);
        }
    }
}

extern "C" void kernel_launch(void* const* d_in, const int* in_sizes, int n_in,
                              void* d_out, int out_size) {
    const float4* x = (const float4*)d_in[0];
    float4* out     = (float4*)d_out;

    const long main_elems = 16L * 16384L * 256L;  // 67108864 floats
    float* tail = ((long)out_size >= main_elems + 4) ? (float*)d_out : nullptr;

    dim3 grid(4, 2048, 1);    // 4 r-tiles/plane, 16*128 planes
    dim3 block(256, 1, 1);
    patch_transpose_kernel<<<grid, block>>>(x, out, tail, main_elems);
}

// round 11
// speedup vs baseline: 1.2226x; 1.2226x over previous
#include <cuda_runtime.h>
#include <cuda_bf16.h>

// PatchEmbed: x (16,64,256,256) f32 -> out (16, 16384, 256) f32  + 4-float shape tail
//
// out[n][j*128 + i][c*4 + ph*2 + pw] = x[n][c][2*i + ph][2*j + pw]
//
// R8 (76.7us, DRAM 79.6%): 32x32 float2 tile, 256 thr, 8 CTAs/SM.
// R10 (97.8us, DRAM 62.9%): 32x128 tile, 6 CTAs/SM -> REGRESSED: lost
//   concurrency + phase mixing; contiguity past 256B is worthless to DRAM.
// R11: keep 64 warps/SM resident but halve barrier count per byte:
//   64(j) x 32(r) float2 tile, 512 threads, 16.9 KB smem -> 4 CTAs/SM,
//   16384 CTAs. float2 smem ops (PAD=1 keeps 2-way conflicts like R8).
//
// float2-unit strides:
//   input : n: 2097152, c: 32768, i: 256, ph: 128, j: 1
//   output: n: 2097152, j: 16384, i: 128, r: 1

#define TR 32
#define TJ 64
#define PAD 1   // row stride 65 float2 = 520 B (8B-aligned; 2-way LDS conflicts)

__global__ __launch_bounds__(512)
void patch_transpose_kernel(const float4* __restrict__ x,
                            float4* __restrict__ out,
                            float* __restrict__ tail,   // null if absent
                            long tail_base) {
    __shared__ float2 tile[TR][TJ + PAD];

    const int t     = blockIdx.x;      // 0..7 : 2 j-tiles x 4 r-tiles
    const int tj    = t & 1;
    const int tr    = t >> 1;
    const int plane = blockIdx.y;      // n*128 + i
    const int n     = plane >> 7;
    const int i     = plane & 127;
    const int tid   = threadIdx.x;     // 0..511

    if (tail && t == 0 && plane == 0 && tid == 0) {
        tail[tail_base + 0] = 16.0f;
        tail[tail_base + 1] = 64.0f;
        tail[tail_base + 2] = 256.0f;
        tail[tail_base + 3] = 256.0f;
    }

    // ---- Load: 32 r-rows x 64 j (float2) ; 512B contiguous per row ----
    {
        const int  rloc = tid >> 4;            // 0..31
        const int  cf4  = tid & 15;            // 0..15
        const int  r    = tr * TR + rloc;      // r = c*2 + ph
        const int  c    = r >> 1;
        const int  ph   = r & 1;
        const long in_f4 = ((long)n * 2097152 + (long)i * 256
                            + (long)c * 32768 + ph * 128) >> 1;
        #pragma unroll
        for (int k = 0; k < 2; k++) {
            const int colf4 = cf4 + k * 16;               // 0..31 within tile
            float4 v = x[in_f4 + tj * 32 + colf4];
            tile[rloc][colf4 * 2 + 0] = make_float2(v.x, v.y);
            tile[rloc][colf4 * 2 + 1] = make_float2(v.z, v.w);
        }
    }
    __syncthreads();

    // ---- Store: 64 j-rows, 256B contiguous r-chunk each ----
    {
        const int  r2   = tid & 15;            // float4 index along r (0..15)
        const int  jrow = tid >> 4;            // 0..31
        const long out_base_f4 = ((long)n * 2097152 + (long)i * 128) >> 1;
        #pragma unroll
        for (int k = 0; k < 2; k++) {
            const int jl = jrow + k * 32;      // 0..63 within tile
            const int j  = tj * TJ + jl;
            float2 a = tile[r2 * 2 + 0][jl];
            float2 b = tile[r2 * 2 + 1][jl];
            out[out_base_f4 + (long)j * 8192 + tr * 16 + r2] =
                make_float4(a.x, a.y, b.x, b.y);
        }
    }
}

extern "C" void kernel_launch(void* const* d_in, const int* in_sizes, int n_in,
                              void* d_out, int out_size) {
    const float4* x = (const float4*)d_in[0];
    float4* out     = (float4*)d_out;

    const long main_elems = 16L * 16384L * 256L;  // 67108864 floats
    float* tail = ((long)out_size >= main_elems + 4) ? (float*)d_out : nullptr;

    dim3 grid(8, 2048, 1);    // 8 tiles/plane, 16*128 planes
    dim3 block(512, 1, 1);
    patch_transpose_kernel<<<grid, block>>>(x, out, tail, main_elems);
}